// round 16
// baseline (speedup 1.0000x reference)
#include <cuda_runtime.h>
#include <cuda_fp16.h>
#include <cstdint>

#define Nn 2048
#define Dd 64
#define Vv 2048
#define TB 128                      // pair tile dim
#define NT (Nn / TB)                // 16
#define NTILES (NT * (NT + 1) / 2)  // 136 triangle tiles
#define PADH 34                     // half2 row stride (even -> LDS.64 aligned)
#define NTHR 512
#define PREB 256                    // k_pre max blocks

// Scratch (no allocations -> __device__ globals). All overwritten per call;
// g_ctr self-resets each run.
__device__ float g_table[(size_t)Vv * Vv];  // fused metric table, 16MB
__device__ float g_part[PREB];              // per-block maxes of map
__device__ float g_rowsum[Nn];              // S[i] = sum_d emb[i][d] (fp32)
__device__ float g_psum[NTILES], g_pcnt[NTILES];
__device__ unsigned g_ctr;                  // zero-init

// ---------------------------------------------------------------------------
__global__ __launch_bounds__(512) void k_pre(const float4* __restrict__ mapd,
                                             const float4* __restrict__ emb) {
    int bid = blockIdx.x, tid = threadIdx.x;
    if (bid < PREB) {
        const float4* p = mapd + (size_t)bid * 4096;   // 512 thr * 8 f4
        float4 x[8];
#pragma unroll
        for (int k = 0; k < 8; k++) x[k] = p[tid + 512 * k];
        float v = 0.0f;
#pragma unroll
        for (int k = 0; k < 8; k++)
            v = fmaxf(v, fmaxf(fmaxf(x[k].x, x[k].y), fmaxf(x[k].z, x[k].w)));
#pragma unroll
        for (int o = 16; o; o >>= 1)
            v = fmaxf(v, __shfl_xor_sync(0xffffffffu, v, o));
        __shared__ float sred[16];
        int lane = tid & 31, w = tid >> 5;
        if (lane == 0) sred[w] = v;
        __syncthreads();
        if (tid == 0) {
            float m = sred[0];
#pragma unroll
            for (int i = 1; i < 16; i++) m = fmaxf(m, sred[i]);
            g_part[bid] = m;
        }
    } else {
        int row = (bid - PREB) * 512 + tid;
        const float4* e = emb + row * (Dd / 4);
        float s = 0.0f;
#pragma unroll
        for (int k = 0; k < Dd / 4; k++) {
            float4 x = e[k];
            s += (x.x + x.y) + (x.z + x.w);
        }
        g_rowsum[row] = s;
    }
}

// ---------------------------------------------------------------------------
// fused table: table = 0.5*tree + (0.5/max)*map. 1024 blocks x 256 thr x 4 f4.
__global__ __launch_bounds__(256) void k_table(const float4* __restrict__ tree,
                                               const float4* __restrict__ mapd) {
    __shared__ float ssc;
    if (threadIdx.x < 32) {
        float v = 0.0f;
#pragma unroll
        for (int k = 0; k < PREB / 32; k++)
            v = fmaxf(v, g_part[threadIdx.x + 32 * k]);
#pragma unroll
        for (int o = 16; o; o >>= 1)
            v = fmaxf(v, __shfl_xor_sync(0xffffffffu, v, o));
        if (threadIdx.x == 0) ssc = 0.5f / v;
    }
    __syncthreads();
    float sc = ssc;
    int base = blockIdx.x * 1024 + threadIdx.x;
    float4 t[4], m[4];
#pragma unroll
    for (int k = 0; k < 4; k++) t[k] = tree[base + 256 * k];
#pragma unroll
    for (int k = 0; k < 4; k++) m[k] = mapd[base + 256 * k];
    float4* tb = (float4*)g_table;
#pragma unroll
    for (int k = 0; k < 4; k++) {
        float4 o;
        o.x = 0.5f * t[k].x + sc * m[k].x;
        o.y = 0.5f * t[k].y + sc * m[k].y;
        o.z = 0.5f * t[k].z + sc * m[k].z;
        o.w = 0.5f * t[k].w + sc * m[k].w;
        tb[base + 256 * k] = o;
    }
}

// ---------------------------------------------------------------------------
extern __shared__ unsigned long long smem_raw[];

// 512 threads, 128x128 tile; thread (tx=tid&15, ty=tid>>4) owns rows ty+32r
// (r<4), cols tx+16c (c<8). fp16 mainloop (HMAX2+HADD2):
// Sum|a-b| = 2*Sum max - S_i - S_j; rowsums stay fp32.
// Table gathers are interleaved through the mainloop in 8 chunks of 4 LDGs
// (to registers, consumed only in the epilogue), so the L1tex wavefront
// drain overlaps the math instead of serializing after it.
__global__ __launch_bounds__(NTHR, 1) void k_main(const int* __restrict__ ids,
                                                  const float2* __restrict__ emb,
                                                  float* __restrict__ out) {
    int tid = threadIdx.x, bid = blockIdx.x;
    int t = bid, bi = 0;
    while (t >= NT - bi) { t -= NT - bi; bi++; }
    int bj = bi + t;
    int ibase = bi * TB, jbase = bj * TB;
    bool offdiag = (bi != bj);

    __half2* sA = (__half2*)smem_raw;               // [128][PADH] h2 (2 elems)
    __half2* sB = sA + TB * PADH;
    int*   sIdI = (int*)(sB + TB * PADH);
    int*   sIdJ = sIdI + TB;
    float* sSA  = (float*)(sIdJ + TB);              // row sums i-tile (fp32)
    float* sSB  = sSA + TB;                         // row sums j-tile
    __shared__ float sred[32];

    int tx = tid & 15, ty = tid >> 4;
    int lane = tid & 31, w = tid >> 5;

    // role-split preload
    if (tid < TB)            sIdI[tid] = ids[ibase + tid];
    else if (tid < 2 * TB)   sIdJ[tid - TB] = ids[jbase + tid - TB];
    else if (tid < 3 * TB)   sSA[tid - 2 * TB] = g_rowsum[ibase + tid - 2 * TB];
    else                     sSB[tid - 3 * TB] = g_rowsum[jbase + tid - 3 * TB];

    // embedding tiles: fp32 -> half2 (coalesced)
    for (int x = tid; x < TB * 32; x += NTHR) {
        int row = x >> 5, k2 = x & 31;
        sA[row * PADH + k2] = __float22half2_rn(emb[(ibase + row) * 32 + k2]);
        sB[row * PADH + k2] = __float22half2_rn(emb[(jbase + row) * 32 + k2]);
    }
    __syncthreads();

    __half2 acc[4][8];
    __half2 zero = __float2half2_rn(0.0f);
#pragma unroll
    for (int r = 0; r < 4; r++)
#pragma unroll
        for (int c = 0; c < 8; c++) acc[r][c] = zero;

    const __half2* sArow = sA + ty * PADH;
    const __half2* sBrow = sB + tx * PADH;

    // mainloop with interleaved gather chunks: before every even k4,
    // issue 4 of the 32 table gathers (pairs p = ch*4 .. ch*4+3).
    float gmet[32];
#pragma unroll
    for (int k4 = 0; k4 < 16; k4++) {
        if ((k4 & 1) == 0) {
            int ch = k4 >> 1;               // 0..7
#pragma unroll
            for (int q = 0; q < 4; q++) {
                int p = ch * 4 + q;         // p = r*8 + c
                int r = p >> 3, c = p & 7;
                const float* ap = g_table + (size_t)sIdI[ty + 32 * r] * Vv
                                + sIdJ[tx + 16 * c];
                asm volatile("ld.global.nc.f32 %0, [%1];"
                             : "=f"(gmet[p]) : "l"(ap));
            }
        }
        __half2 b0[8], b1[8];
#pragma unroll
        for (int c = 0; c < 8; c++) {
            float2 tb2 = *(const float2*)(sBrow + (16 * c) * PADH + 2 * k4);
            b0[c] = *(__half2*)&tb2.x;
            b1[c] = *(__half2*)&tb2.y;
        }
#pragma unroll
        for (int r = 0; r < 4; r++) {
            float2 ta2 = *(const float2*)(sArow + (32 * r) * PADH + 2 * k4);
            __half2 a0 = *(__half2*)&ta2.x, a1 = *(__half2*)&ta2.y;
#pragma unroll
            for (int c = 0; c < 8; c++) {
                acc[r][c] = __hadd2(acc[r][c], __hmax2(a0, b0[c]));
                acc[r][c] = __hadd2(acc[r][c], __hmax2(a1, b1[c]));
            }
        }
    }

    // ---- epilogue: ed = (2*sum(max) - S_i - S_j)/64 ----
    float loss = 0.0f, cnt = 0.0f;
    const float inv64 = 1.0f / 64.0f;
#pragma unroll
    for (int r = 0; r < 4; r++) {
        int ir = ty + 32 * r;
        int idi = sIdI[ir];
        int gi  = ibase + ir;
        float Si = sSA[ir];
#pragma unroll
        for (int c = 0; c < 8; c++) {
            int jc = tx + 16 * c;
            int idj = sIdJ[jc];
            int gj  = jbase + jc;
            if ((offdiag || gi < gj) && idi != idj) {
                float2 s2 = __half22float2(acc[r][c]);
                float ed = (2.0f * (s2.x + s2.y) - Si - sSB[jc]) * inv64;
                loss += fabsf(ed - gmet[r * 8 + c]);
                cnt += 1.0f;
            }
        }
    }

#pragma unroll
    for (int o = 16; o; o >>= 1) {
        loss += __shfl_xor_sync(0xffffffffu, loss, o);
        cnt  += __shfl_xor_sync(0xffffffffu, cnt, o);
    }
    if (lane == 0) { sred[w] = loss; sred[16 + w] = cnt; }
    __syncthreads();
    if (tid == 0) {
        float L = 0.0f, C = 0.0f;
#pragma unroll
        for (int i = 0; i < 16; i++) { L += sred[i]; C += sred[16 + i]; }
        g_psum[bid] = L;
        g_pcnt[bid] = C;
        __threadfence();
        unsigned done = atomicAdd(&g_ctr, 1u);
        sred[0] = (done == NTILES - 1) ? 1.0f : 0.0f;
    }
    __syncthreads();
    if (sred[0] != 0.0f) {            // last block folds the final reduction
        __threadfence();
        float L = 0.0f, C = 0.0f;
        if (tid < NTILES) {
            L = *((volatile float*)g_psum + tid);
            C = *((volatile float*)g_pcnt + tid);
        }
#pragma unroll
        for (int o = 16; o; o >>= 1) {
            L += __shfl_xor_sync(0xffffffffu, L, o);
            C += __shfl_xor_sync(0xffffffffu, C, o);
        }
        if (lane == 0) { sred[w] = L; sred[16 + w] = C; }
        __syncthreads();
        if (tid == 0) {
            float LL = 0.0f, CC = 0.0f;
#pragma unroll
            for (int i = 0; i < 16; i++) { LL += sred[i]; CC += sred[16 + i]; }
            out[0] = LL / CC;
            g_ctr = 0u;               // self-reset for next graph replay
        }
    }
}

// ---------------------------------------------------------------------------
extern "C" void kernel_launch(void* const* d_in, const int* in_sizes, int n_in,
                              void* d_out, int out_size) {
    const int*   ids  = (const int*)d_in[0];
    const float* emb  = (const float*)d_in[1];
    const float* tree = (const float*)d_in[2];
    const float* mapd = (const float*)d_in[3];
    float* out = (float*)d_out;

    // smem: h2 tiles 2*128*34*4 = 34816 + ids 1024 + rowsums 1024 = 36864 B
    const int SMEM_BYTES = 2 * TB * PADH * 4 + 2 * TB * 4 + 2 * TB * 4;
    cudaFuncSetAttribute(k_main, cudaFuncAttributeMaxDynamicSharedMemorySize,
                         SMEM_BYTES);

    k_pre<<<PREB + 4, 512>>>((const float4*)mapd, (const float4*)emb);
    k_table<<<1024, 256>>>((const float4*)tree, (const float4*)mapd);
    k_main<<<NTILES, NTHR, SMEM_BYTES>>>(ids, (const float2*)emb, out);
}

// round 17
// speedup vs baseline: 1.4321x; 1.4321x over previous
#include <cuda_runtime.h>
#include <cuda_fp16.h>
#include <cstdint>

#define Nn 2048
#define Dd 64
#define Vv 2048
#define TB 128                      // pair tile dim
#define NT (Nn / TB)                // 16
#define NTILES (NT * (NT + 1) / 2)  // 136 triangle tiles
#define PADH 34                     // half2 row stride (even -> LDS.64 aligned)
#define NTHR 512
#define PREB 256                    // k_pre max blocks

// Scratch (no allocations -> __device__ globals). All overwritten per call;
// g_ctr self-resets each run.
__device__ float g_table[(size_t)Vv * Vv];  // fused metric table, 16MB
__device__ float g_part[PREB];              // per-block maxes of map
__device__ float g_rowsum[Nn];              // S[i] = sum_d emb[i][d] (fp32)
__device__ float g_psum[NTILES], g_pcnt[NTILES];
__device__ unsigned g_ctr;                  // zero-init

// ---------------------------------------------------------------------------
__global__ __launch_bounds__(512) void k_pre(const float4* __restrict__ mapd,
                                             const float4* __restrict__ emb) {
    int bid = blockIdx.x, tid = threadIdx.x;
    if (bid < PREB) {
        const float4* p = mapd + (size_t)bid * 4096;   // 512 thr * 8 f4
        float4 x[8];
#pragma unroll
        for (int k = 0; k < 8; k++) x[k] = p[tid + 512 * k];
        float v = 0.0f;
#pragma unroll
        for (int k = 0; k < 8; k++)
            v = fmaxf(v, fmaxf(fmaxf(x[k].x, x[k].y), fmaxf(x[k].z, x[k].w)));
#pragma unroll
        for (int o = 16; o; o >>= 1)
            v = fmaxf(v, __shfl_xor_sync(0xffffffffu, v, o));
        __shared__ float sred[16];
        int lane = tid & 31, w = tid >> 5;
        if (lane == 0) sred[w] = v;
        __syncthreads();
        if (tid == 0) {
            float m = sred[0];
#pragma unroll
            for (int i = 1; i < 16; i++) m = fmaxf(m, sred[i]);
            g_part[bid] = m;
        }
    } else {
        int row = (bid - PREB) * 512 + tid;
        const float4* e = emb + row * (Dd / 4);
        float s = 0.0f;
#pragma unroll
        for (int k = 0; k < Dd / 4; k++) {
            float4 x = e[k];
            s += (x.x + x.y) + (x.z + x.w);
        }
        g_rowsum[row] = s;
    }
}

// ---------------------------------------------------------------------------
// fused table: table = 0.5*tree + (0.5/max)*map. 1024 blocks x 256 thr x 4 f4.
__global__ __launch_bounds__(256) void k_table(const float4* __restrict__ tree,
                                               const float4* __restrict__ mapd) {
    __shared__ float ssc;
    if (threadIdx.x < 32) {
        float v = 0.0f;
#pragma unroll
        for (int k = 0; k < PREB / 32; k++)
            v = fmaxf(v, g_part[threadIdx.x + 32 * k]);
#pragma unroll
        for (int o = 16; o; o >>= 1)
            v = fmaxf(v, __shfl_xor_sync(0xffffffffu, v, o));
        if (threadIdx.x == 0) ssc = 0.5f / v;
    }
    __syncthreads();
    float sc = ssc;
    int base = blockIdx.x * 1024 + threadIdx.x;
    float4 t[4], m[4];
#pragma unroll
    for (int k = 0; k < 4; k++) t[k] = tree[base + 256 * k];
#pragma unroll
    for (int k = 0; k < 4; k++) m[k] = mapd[base + 256 * k];
    float4* tb = (float4*)g_table;
#pragma unroll
    for (int k = 0; k < 4; k++) {
        float4 o;
        o.x = 0.5f * t[k].x + sc * m[k].x;
        o.y = 0.5f * t[k].y + sc * m[k].y;
        o.z = 0.5f * t[k].z + sc * m[k].z;
        o.w = 0.5f * t[k].w + sc * m[k].w;
        tb[base + 256 * k] = o;
    }
}

// ---------------------------------------------------------------------------
extern __shared__ unsigned long long smem_raw[];

// 512 threads, 128x128 tile; thread (tx=tid&15, ty=tid>>4) owns rows ty+32r
// (r<4), cols tx+16c (c<8). fp16 mainloop (HMAX2+HADD2):
// Sum|a-b| = 2*Sum max - S_i - S_j; rowsums stay fp32.
// All 32 table gathers are issued BEFORE the mainloop (after the tile
// loads, so tile LDGs don't queue behind gather wavefronts); the full
// mainloop (~9us of math) covers the full L1tex gather drain.
__global__ __launch_bounds__(NTHR, 1) void k_main(const int* __restrict__ ids,
                                                  const float2* __restrict__ emb,
                                                  float* __restrict__ out) {
    int tid = threadIdx.x, bid = blockIdx.x;
    int t = bid, bi = 0;
    while (t >= NT - bi) { t -= NT - bi; bi++; }
    int bj = bi + t;
    int ibase = bi * TB, jbase = bj * TB;
    bool offdiag = (bi != bj);

    __half2* sA = (__half2*)smem_raw;               // [128][PADH] h2 (2 elems)
    __half2* sB = sA + TB * PADH;
    int*   sIdI = (int*)(sB + TB * PADH);
    int*   sIdJ = sIdI + TB;
    float* sSA  = (float*)(sIdJ + TB);              // row sums i-tile (fp32)
    float* sSB  = sSA + TB;                         // row sums j-tile
    __shared__ float sred[32];

    int tx = tid & 15, ty = tid >> 4;
    int lane = tid & 31, w = tid >> 5;

    // role-split preload
    if (tid < TB)            sIdI[tid] = ids[ibase + tid];
    else if (tid < 2 * TB)   sIdJ[tid - TB] = ids[jbase + tid - TB];
    else if (tid < 3 * TB)   sSA[tid - 2 * TB] = g_rowsum[ibase + tid - 2 * TB];
    else                     sSB[tid - 3 * TB] = g_rowsum[jbase + tid - 3 * TB];

    // embedding tiles: fp32 -> half2 (coalesced)
    for (int x = tid; x < TB * 32; x += NTHR) {
        int row = x >> 5, k2 = x & 31;
        sA[row * PADH + k2] = __float22half2_rn(emb[(ibase + row) * 32 + k2]);
        sB[row * PADH + k2] = __float22half2_rn(emb[(jbase + row) * 32 + k2]);
    }
    __syncthreads();

    // ---- issue ALL 32 table gathers now; math below covers the drain ----
    float gmet[32];
#pragma unroll
    for (int r = 0; r < 4; r++) {
        const float* rowp = g_table + (size_t)sIdI[ty + 32 * r] * Vv;
#pragma unroll
        for (int c = 0; c < 8; c++) {
            asm volatile("ld.global.nc.f32 %0, [%1];"
                         : "=f"(gmet[r * 8 + c])
                         : "l"(rowp + sIdJ[tx + 16 * c]));
        }
    }

    __half2 acc[4][8];
    __half2 zero = __float2half2_rn(0.0f);
#pragma unroll
    for (int r = 0; r < 4; r++)
#pragma unroll
        for (int c = 0; c < 8; c++) acc[r][c] = zero;

    const __half2* sArow = sA + ty * PADH;
    const __half2* sBrow = sB + tx * PADH;

    // ---- mainloop: k4 = 0..15 (each k4 = 4 elems = 2 h2 via LDS.64) ----
#pragma unroll 4
    for (int k4 = 0; k4 < 16; k4++) {
        __half2 b0[8], b1[8];
#pragma unroll
        for (int c = 0; c < 8; c++) {
            float2 tb2 = *(const float2*)(sBrow + (16 * c) * PADH + 2 * k4);
            b0[c] = *(__half2*)&tb2.x;
            b1[c] = *(__half2*)&tb2.y;
        }
#pragma unroll
        for (int r = 0; r < 4; r++) {
            float2 ta2 = *(const float2*)(sArow + (32 * r) * PADH + 2 * k4);
            __half2 a0 = *(__half2*)&ta2.x, a1 = *(__half2*)&ta2.y;
#pragma unroll
            for (int c = 0; c < 8; c++) {
                acc[r][c] = __hadd2(acc[r][c], __hmax2(a0, b0[c]));
                acc[r][c] = __hadd2(acc[r][c], __hmax2(a1, b1[c]));
            }
        }
    }

    // ---- epilogue: ed = (2*sum(max) - S_i - S_j)/64 ----
    float loss = 0.0f, cnt = 0.0f;
    const float inv64 = 1.0f / 64.0f;
#pragma unroll
    for (int r = 0; r < 4; r++) {
        int ir = ty + 32 * r;
        int idi = sIdI[ir];
        int gi  = ibase + ir;
        float Si = sSA[ir];
#pragma unroll
        for (int c = 0; c < 8; c++) {
            int jc = tx + 16 * c;
            int idj = sIdJ[jc];
            int gj  = jbase + jc;
            if ((offdiag || gi < gj) && idi != idj) {
                float2 s2 = __half22float2(acc[r][c]);
                float ed = (2.0f * (s2.x + s2.y) - Si - sSB[jc]) * inv64;
                loss += fabsf(ed - gmet[r * 8 + c]);
                cnt += 1.0f;
            }
        }
    }

#pragma unroll
    for (int o = 16; o; o >>= 1) {
        loss += __shfl_xor_sync(0xffffffffu, loss, o);
        cnt  += __shfl_xor_sync(0xffffffffu, cnt, o);
    }
    if (lane == 0) { sred[w] = loss; sred[16 + w] = cnt; }
    __syncthreads();
    if (tid == 0) {
        float L = 0.0f, C = 0.0f;
#pragma unroll
        for (int i = 0; i < 16; i++) { L += sred[i]; C += sred[16 + i]; }
        g_psum[bid] = L;
        g_pcnt[bid] = C;
        __threadfence();
        unsigned done = atomicAdd(&g_ctr, 1u);
        sred[0] = (done == NTILES - 1) ? 1.0f : 0.0f;
    }
    __syncthreads();
    if (sred[0] != 0.0f) {            // last block folds the final reduction
        __threadfence();
        float L = 0.0f, C = 0.0f;
        if (tid < NTILES) {
            L = *((volatile float*)g_psum + tid);
            C = *((volatile float*)g_pcnt + tid);
        }
#pragma unroll
        for (int o = 16; o; o >>= 1) {
            L += __shfl_xor_sync(0xffffffffu, L, o);
            C += __shfl_xor_sync(0xffffffffu, C, o);
        }
        if (lane == 0) { sred[w] = L; sred[16 + w] = C; }
        __syncthreads();
        if (tid == 0) {
            float LL = 0.0f, CC = 0.0f;
#pragma unroll
            for (int i = 0; i < 16; i++) { LL += sred[i]; CC += sred[16 + i]; }
            out[0] = LL / CC;
            g_ctr = 0u;               // self-reset for next graph replay
        }
    }
}

// ---------------------------------------------------------------------------
extern "C" void kernel_launch(void* const* d_in, const int* in_sizes, int n_in,
                              void* d_out, int out_size) {
    const int*   ids  = (const int*)d_in[0];
    const float* emb  = (const float*)d_in[1];
    const float* tree = (const float*)d_in[2];
    const float* mapd = (const float*)d_in[3];
    float* out = (float*)d_out;

    // smem: h2 tiles 2*128*34*4 = 34816 + ids 1024 + rowsums 1024 = 36864 B
    const int SMEM_BYTES = 2 * TB * PADH * 4 + 2 * TB * 4 + 2 * TB * 4;
    cudaFuncSetAttribute(k_main, cudaFuncAttributeMaxDynamicSharedMemorySize,
                         SMEM_BYTES);

    k_pre<<<PREB + 4, 512>>>((const float4*)mapd, (const float4*)emb);
    k_table<<<1024, 256>>>((const float4*)tree, (const float4*)mapd);
    k_main<<<NTILES, NTHR, SMEM_BYTES>>>(ids, (const float2*)emb, out);
}